// round 1
// baseline (speedup 1.0000x reference)
#include <cuda_runtime.h>

// ---------------- scratch (no allocations allowed) ----------------
__device__ float g_y1a[2*32*4096];      // after pointwise squeeze (b,32,64,64)
__device__ float g_y3[2*64*1024];      // after depthwise+perm (b,64,32,32)
__device__ float g_y5[2*64*1024];      // after channel attn + nidx perm
__device__ float g_os[2*64*2*1024];    // spatial attn output per head (b,h,d,n)

__device__ __forceinline__ float ex2f(float x){
  float y; asm("ex2.approx.ftz.f32 %0, %1;" : "=f"(y) : "f"(x)); return y;
}

// ---------------- K1: pointwise squeeze 64->32 over (2,64,64,64) ----------------
__global__ void k_squeeze1(const float* __restrict__ x, const float* __restrict__ w,
                           const float* __restrict__ bias){
  __shared__ float ws[512];
  int t = threadIdx.x;
  int og = blockIdx.y, b = blockIdx.z;
  for (int i=t;i<512;i+=256) ws[i] = w[og*512 + i];
  __syncthreads();
  int pos = blockIdx.x*256 + t;
  float acc[8];
  #pragma unroll
  for (int oo=0;oo<8;oo++) acc[oo] = bias[og*8+oo];
  const float* xp = x + b*262144 + pos;
  #pragma unroll 4
  for (int c=0;c<64;c++){
    float xv = xp[c<<12];
    #pragma unroll
    for (int oo=0;oo<8;oo++) acc[oo] = fmaf(xv, ws[oo*64+c], acc[oo]);
  }
  #pragma unroll
  for (int oo=0;oo<8;oo++) g_y1a[((b*32+og*8+oo)<<12)+pos] = acc[oo];
}

// ---------------- K2: depthwise 2x2 stride2 + channel perm idx ----------------
__global__ void k_squeeze2(const float* __restrict__ w2, const float* __restrict__ b2){
  int idx = blockIdx.x*256 + threadIdx.x;   // (b,p,n) : 2*64*1024
  int n = idx & 1023, p = (idx>>10)&63, b = idx>>16;
  int oc = (p>>1) | ((p&1)<<5);             // idx permutation
  int g = oc>>1;
  int hh = n>>5, ww = n&31;
  const float* src = g_y1a + ((b*32+g)<<12) + ((hh<<1)<<6) + (ww<<1);
  const float* wv = w2 + oc*4;
  g_y3[idx] = b2[oc] + src[0]*wv[0] + src[1]*wv[1] + src[64]*wv[2] + src[65]*wv[3];
}

// ---------------- K3: channel attention via moments; writes y5 (nidx-permuted) ----------------
__global__ void k_chattn(const float* __restrict__ wqkv, const float* __restrict__ bqkv,
                         const float* __restrict__ tvec, const float* __restrict__ wf,
                         const float* __restrict__ bf){
  int h2 = blockIdx.x, b = blockIdx.y;       // h2 in [0,32): heads h2 and h2+32
  __shared__ float ch0[1024], ch1[1024];
  __shared__ float red[8][5];
  __shared__ float coef[6];
  int t = threadIdx.x;
  const float* base = g_y3 + (b*64 + 2*h2)*1024;
  float s0=0.f,s1=0.f,m00=0.f,m01=0.f,m11=0.f;
  for (int i=t;i<1024;i+=256){
    float a = base[i], c = base[1024+i];
    ch0[i]=a; ch1[i]=c;
    s0+=a; s1+=c; m00=fmaf(a,a,m00); m01=fmaf(a,c,m01); m11=fmaf(c,c,m11);
  }
  #pragma unroll
  for (int off=16;off;off>>=1){
    s0 += __shfl_down_sync(0xffffffffu,s0,off);
    s1 += __shfl_down_sync(0xffffffffu,s1,off);
    m00+= __shfl_down_sync(0xffffffffu,m00,off);
    m01+= __shfl_down_sync(0xffffffffu,m01,off);
    m11+= __shfl_down_sync(0xffffffffu,m11,off);
  }
  if ((t&31)==0){ int w=t>>5; red[w][0]=s0; red[w][1]=s1; red[w][2]=m00; red[w][3]=m01; red[w][4]=m11; }
  __syncthreads();
  if (t==0){
    float S1v[2]={0.f,0.f}, S200=0.f,S201=0.f,S211=0.f;
    for (int w=0;w<8;w++){ S1v[0]+=red[w][0]; S1v[1]+=red[w][1]; S200+=red[w][2]; S201+=red[w][3]; S211+=red[w][4]; }
    float S2[2][2]; S2[0][0]=S200; S2[0][1]=S201; S2[1][0]=S201; S2[1][1]=S211;
    float A[2]={0.f,0.f}, Bc[2]={0.f,0.f}, Cc[2]={0.f,0.f};
    #pragma unroll
    for (int ee=0;ee<2;ee++){
      int h = h2 + 32*ee;
      float th = tvec[h];
      float aq[2],bq[2],ak[2],bk[2],av[2],bv[2],nq[2],nk[2];
      #pragma unroll
      for (int d=0;d<2;d++){
        int cd = 2*h2+d;
        aq[d]=wqkv[cd*6+ee];   bq[d]=bqkv[cd*6+ee];
        ak[d]=wqkv[cd*6+2+ee]; bk[d]=bqkv[cd*6+2+ee];
        av[d]=wqkv[cd*6+4+ee]; bv[d]=bqkv[cd*6+4+ee];
        nq[d]=fmaxf(sqrtf(fmaxf(aq[d]*aq[d]*S2[d][d]+2.f*aq[d]*bq[d]*S1v[d]+bq[d]*bq[d]*1024.f,0.f)),1e-12f);
        nk[d]=fmaxf(sqrtf(fmaxf(ak[d]*ak[d]*S2[d][d]+2.f*ak[d]*bk[d]*S1v[d]+bk[d]*bk[d]*1024.f,0.f)),1e-12f);
      }
      #pragma unroll
      for (int d=0;d<2;d++){
        float l[2];
        #pragma unroll
        for (int e=0;e<2;e++){
          float dot = aq[d]*ak[e]*S2[d][e] + aq[d]*bk[e]*S1v[d] + bq[d]*ak[e]*S1v[e] + bq[d]*bk[e]*1024.f;
          l[e] = dot/(nq[d]*nk[e])*th;
        }
        float mx = fmaxf(l[0],l[1]);
        float p0 = __expf(l[0]-mx), p1 = __expf(l[1]-mx);
        float inv = 1.f/(p0+p1);
        float a0 = p0*inv, a1 = p1*inv;
        int c = 2*h2+d;
        float wfv = wf[c*2+ee];
        A[d]  = fmaf(wfv, a0*av[0], A[d]);
        Bc[d] = fmaf(wfv, a1*av[1], Bc[d]);
        Cc[d] = fmaf(wfv, fmaf(a0,bv[0],a1*bv[1]), Cc[d]);
      }
    }
    coef[0]=A[0]; coef[1]=Bc[0]; coef[2]=Cc[0]+bf[2*h2];
    coef[3]=A[1]; coef[4]=Bc[1]; coef[5]=Cc[1]+bf[2*h2+1];
  }
  __syncthreads();
  float A0=coef[0],B0=coef[1],C0=coef[2],A1=coef[3],B1=coef[4],C1=coef[5];
  // y4 channel c -> y5 channel (c%2)*32 + c/2 ; here c = 2*h2+d  => p' = d*32 + h2
  float* o0 = g_y5 + (b*64 + h2)*1024;
  float* o1 = g_y5 + (b*64 + 32 + h2)*1024;
  for (int i=t;i<1024;i+=256){
    float a = ch0[i], c = ch1[i];
    o0[i] = fmaf(A0,a,fmaf(B0,c,C0));
    o1[i] = fmaf(A1,a,fmaf(B1,c,C1));
  }
}

// ---------------- K4: spatial attention (d=2, N=1024 per head) ----------------
__global__ void k_spattn(const float* __restrict__ wqkv, const float* __restrict__ bqkv,
                         const float* __restrict__ tvec){
  int h = blockIdx.x, b = blockIdx.y;
  int ee = h>>5;
  int c0 = (h&31)*2;
  __shared__ float4 kv[1024];     // (kx*t*log2e/|k|, ky*t*log2e/|k|, v0, v1)
  __shared__ float2 qs[1024];     // normalized q
  int t = threadIdx.x;
  float aq0=wqkv[c0*6+ee],     bq0=bqkv[c0*6+ee];
  float aq1=wqkv[(c0+1)*6+ee], bq1=bqkv[(c0+1)*6+ee];
  float ak0=wqkv[c0*6+2+ee],     bk0=bqkv[c0*6+2+ee];
  float ak1=wqkv[(c0+1)*6+2+ee], bk1=bqkv[(c0+1)*6+2+ee];
  float av0=wqkv[c0*6+4+ee],     bv0=bqkv[c0*6+4+ee];
  float av1=wqkv[(c0+1)*6+4+ee], bv1=bqkv[(c0+1)*6+4+ee];
  float tsc = tvec[h]*1.4426950408889634f;
  const float* x0p = g_y5 + (b*64 + c0)*1024;
  const float* x1p = x0p + 1024;
  for (int i=t;i<1024;i+=256){
    float x0=x0p[i], x1=x1p[i];
    float qx = fmaf(aq0,x0,bq0), qy = fmaf(aq1,x1,bq1);
    float qi = 1.f/fmaxf(sqrtf(qx*qx+qy*qy),1e-12f);
    qs[i] = make_float2(qx*qi, qy*qi);
    float kx = fmaf(ak0,x0,bk0), ky = fmaf(ak1,x1,bk1);
    float ki = tsc/fmaxf(sqrtf(kx*kx+ky*ky),1e-12f);
    kv[i] = make_float4(kx*ki, ky*ki, fmaf(av0,x0,bv0), fmaf(av1,x1,bv1));
  }
  __syncthreads();
  float qx[4],qy[4],den[4],ox[4],oy[4];
  #pragma unroll
  for (int q=0;q<4;q++){ float2 qq = qs[t+q*256]; qx[q]=qq.x; qy[q]=qq.y; den[q]=0.f; ox[q]=0.f; oy[q]=0.f; }
  #pragma unroll 4
  for (int m=0;m<1024;m++){
    float4 kk = kv[m];
    #pragma unroll
    for (int q=0;q<4;q++){
      float e = ex2f(fmaf(qy[q],kk.y, qx[q]*kk.x));   // |arg| <= |t|*log2e, no overflow; shift cancels in ratio
      den[q] += e;
      ox[q] = fmaf(e,kk.z,ox[q]);
      oy[q] = fmaf(e,kk.w,oy[q]);
    }
  }
  float* ob = g_os + (b*64+h)*2048;
  #pragma unroll
  for (int q=0;q<4;q++){
    int n = t+q*256;
    float inv = 1.f/den[q];
    ob[n]      = ox[q]*inv;
    ob[1024+n] = oy[q]*inv;
  }
}

// ---------------- K5: group fuse + un1 (grouped 1x1) + pixel shuffle + un2 ----------------
__global__ void k_fuse(const float* __restrict__ wf, const float* __restrict__ bf,
                       const float* __restrict__ w1, const float* __restrict__ b1,
                       const float* __restrict__ w2, const float* __restrict__ b2,
                       float* __restrict__ out){
  __shared__ float y6s[64][65];
  __shared__ float4 wu2[512];     // w_un2 (64x32) as float4
  int t = threadIdx.x;
  int b = blockIdx.y;
  int n0 = blockIdx.x*64;
  for (int i=t;i<512;i+=256) wu2[i] = ((const float4*)w2)[i];
  for (int j=t;j<4096;j+=256){
    int pos = j&63, c = j>>6;
    int n = n0+pos;
    float o0 = g_os[((b*64 + (c>>1))*2 + (c&1))*1024 + n];
    float o1 = g_os[((b*64 + 32 + (c>>1))*2 + (c&1))*1024 + n];
    y6s[pos][c] = fmaf(wf[c*2],o0, fmaf(wf[c*2+1],o1, bf[c]));
  }
  __syncthreads();
  int pos = t>>2, r = t&3;        // r = r1*2 + r2 sub-pixel
  float z[32];
  #pragma unroll
  for (int cc=0;cc<32;cc++){
    int o2 = 4*cc+r;
    z[cc] = fmaf(w1[o2*2], y6s[pos][2*cc], fmaf(w1[o2*2+1], y6s[pos][2*cc+1], b1[o2]));
  }
  int n = n0+pos;
  int hh = n>>5, ww = n&31;
  float* outp = out + (b<<18) + ((2*hh + (r>>1))<<6) + 2*ww + (r&1);
  #pragma unroll 2
  for (int o=0;o<64;o++){
    float acc = b2[o];
    #pragma unroll
    for (int q8=0;q8<8;q8++){
      float4 wv = wu2[o*8+q8];
      acc = fmaf(wv.x,z[q8*4+0], fmaf(wv.y,z[q8*4+1], fmaf(wv.z,z[q8*4+2], fmaf(wv.w,z[q8*4+3], acc))));
    }
    outp[o<<12] = acc;
  }
}

extern "C" void kernel_launch(void* const* d_in, const int* in_sizes, int n_in,
                              void* d_out, int out_size){
  const float* x       = (const float*)d_in[0];
  const float* w_sq1   = (const float*)d_in[1];
  const float* b_sq1   = (const float*)d_in[2];
  const float* w_sq2   = (const float*)d_in[3];
  const float* b_sq2   = (const float*)d_in[4];
  const float* ca_wqkv = (const float*)d_in[5];
  const float* ca_bqkv = (const float*)d_in[6];
  const float* ca_t    = (const float*)d_in[7];
  const float* ca_wf   = (const float*)d_in[8];
  const float* ca_bf   = (const float*)d_in[9];
  const float* sa_wqkv = (const float*)d_in[10];
  const float* sa_bqkv = (const float*)d_in[11];
  const float* sa_t    = (const float*)d_in[12];
  const float* sa_wf   = (const float*)d_in[13];
  const float* sa_bf   = (const float*)d_in[14];
  const float* w_un1   = (const float*)d_in[15];
  const float* b_un1   = (const float*)d_in[16];
  const float* w_un2   = (const float*)d_in[17];
  const float* b_un2   = (const float*)d_in[18];
  float* out = (float*)d_out;

  k_squeeze1<<<dim3(16,4,2),256>>>(x, w_sq1, b_sq1);
  k_squeeze2<<<512,256>>>(w_sq2, b_sq2);
  k_chattn<<<dim3(32,2),256>>>(ca_wqkv, ca_bqkv, ca_t, ca_wf, ca_bf);
  k_spattn<<<dim3(64,2),256>>>(sa_wqkv, sa_bqkv, sa_t);
  k_fuse<<<dim3(16,2),256>>>(sa_wf, sa_bf, w_un1, b_un1, w_un2, b_un2, out);
}

// round 2
// speedup vs baseline: 1.0664x; 1.0664x over previous
#include <cuda_runtime.h>

// ---------------- scratch (no allocations allowed) ----------------
__device__ float g_y1a[2*32*4096];     // after pointwise squeeze (b,32,64,64)
__device__ float g_y5[2*64*1024];      // after channel attn + nidx perm
__device__ float g_os[2*64*2*1024];    // spatial attn output per head (b,h,d,n)

// ---------------- K1: pointwise squeeze 64->32 over (2,64,64,64) ----------------
__global__ void k_squeeze1(const float* __restrict__ x, const float* __restrict__ w,
                           const float* __restrict__ bias){
  __shared__ float ws[512];
  int t = threadIdx.x;
  int og = blockIdx.y, b = blockIdx.z;
  for (int i=t;i<512;i+=256) ws[i] = w[og*512 + i];
  __syncthreads();
  int pos = blockIdx.x*256 + t;
  float acc[8];
  #pragma unroll
  for (int oo=0;oo<8;oo++) acc[oo] = bias[og*8+oo];
  const float* xp = x + b*262144 + pos;
  #pragma unroll 4
  for (int c=0;c<64;c++){
    float xv = xp[c<<12];
    #pragma unroll
    for (int oo=0;oo<8;oo++) acc[oo] = fmaf(xv, ws[oo*64+c], acc[oo]);
  }
  #pragma unroll
  for (int oo=0;oo<8;oo++) g_y1a[((b*32+og*8+oo)<<12)+pos] = acc[oo];
}

// ---------------- K2: depthwise 2x2 s2 (fused) + channel attention via moments ----------------
__global__ void k_chattn(const float* __restrict__ w2, const float* __restrict__ b2,
                         const float* __restrict__ wqkv, const float* __restrict__ bqkv,
                         const float* __restrict__ tvec, const float* __restrict__ wf,
                         const float* __restrict__ bf){
  int h2 = blockIdx.x, b = blockIdx.y;       // h2 in [0,32)
  __shared__ float ch0[1024], ch1[1024];
  __shared__ float red[8][5];
  __shared__ float coef[6];
  int t = threadIdx.x;
  // y3 channel p=2h2   -> oc = h2      (group g0 = h2>>1)
  // y3 channel p=2h2+1 -> oc = h2+32   (group g1 = 16 + (h2>>1))
  int oc0 = h2, oc1 = h2 + 32;
  int g0 = oc0>>1, g1 = oc1>>1;
  const float* s0b = g_y1a + ((b*32+g0)<<12);
  const float* s1b = g_y1a + ((b*32+g1)<<12);
  float w00=w2[oc0*4],w01=w2[oc0*4+1],w02=w2[oc0*4+2],w03=w2[oc0*4+3],bb0=b2[oc0];
  float w10=w2[oc1*4],w11=w2[oc1*4+1],w12=w2[oc1*4+2],w13=w2[oc1*4+3],bb1=b2[oc1];
  float s0=0.f,s1=0.f,m00=0.f,m01=0.f,m11=0.f;
  for (int i=t;i<1024;i+=256){
    int hh=i>>5, ww=i&31;
    int off = (hh<<7) + (ww<<1);
    const float* p0 = s0b + off;
    const float* p1 = s1b + off;
    float a = bb0 + p0[0]*w00 + p0[1]*w01 + p0[64]*w02 + p0[65]*w03;
    float c = bb1 + p1[0]*w10 + p1[1]*w11 + p1[64]*w12 + p1[65]*w13;
    ch0[i]=a; ch1[i]=c;
    s0+=a; s1+=c; m00=fmaf(a,a,m00); m01=fmaf(a,c,m01); m11=fmaf(c,c,m11);
  }
  #pragma unroll
  for (int off=16;off;off>>=1){
    s0 += __shfl_down_sync(0xffffffffu,s0,off);
    s1 += __shfl_down_sync(0xffffffffu,s1,off);
    m00+= __shfl_down_sync(0xffffffffu,m00,off);
    m01+= __shfl_down_sync(0xffffffffu,m01,off);
    m11+= __shfl_down_sync(0xffffffffu,m11,off);
  }
  if ((t&31)==0){ int w=t>>5; red[w][0]=s0; red[w][1]=s1; red[w][2]=m00; red[w][3]=m01; red[w][4]=m11; }
  __syncthreads();
  if (t==0){
    float S1v[2]={0.f,0.f}, S200=0.f,S201=0.f,S211=0.f;
    for (int w=0;w<8;w++){ S1v[0]+=red[w][0]; S1v[1]+=red[w][1]; S200+=red[w][2]; S201+=red[w][3]; S211+=red[w][4]; }
    float S2[2][2]; S2[0][0]=S200; S2[0][1]=S201; S2[1][0]=S201; S2[1][1]=S211;
    float A[2]={0.f,0.f}, Bc[2]={0.f,0.f}, Cc[2]={0.f,0.f};
    #pragma unroll
    for (int ee=0;ee<2;ee++){
      int h = h2 + 32*ee;
      float th = tvec[h];
      float aq[2],bq[2],ak[2],bk[2],av[2],bv[2],nq[2],nk[2];
      #pragma unroll
      for (int d=0;d<2;d++){
        int cd = 2*h2+d;
        aq[d]=wqkv[cd*6+ee];   bq[d]=bqkv[cd*6+ee];
        ak[d]=wqkv[cd*6+2+ee]; bk[d]=bqkv[cd*6+2+ee];
        av[d]=wqkv[cd*6+4+ee]; bv[d]=bqkv[cd*6+4+ee];
        nq[d]=fmaxf(sqrtf(fmaxf(aq[d]*aq[d]*S2[d][d]+2.f*aq[d]*bq[d]*S1v[d]+bq[d]*bq[d]*1024.f,0.f)),1e-12f);
        nk[d]=fmaxf(sqrtf(fmaxf(ak[d]*ak[d]*S2[d][d]+2.f*ak[d]*bk[d]*S1v[d]+bk[d]*bk[d]*1024.f,0.f)),1e-12f);
      }
      #pragma unroll
      for (int d=0;d<2;d++){
        float l[2];
        #pragma unroll
        for (int e=0;e<2;e++){
          float dot = aq[d]*ak[e]*S2[d][e] + aq[d]*bk[e]*S1v[d] + bq[d]*ak[e]*S1v[e] + bq[d]*bk[e]*1024.f;
          l[e] = dot/(nq[d]*nk[e])*th;
        }
        float mx = fmaxf(l[0],l[1]);
        float p0 = __expf(l[0]-mx), p1 = __expf(l[1]-mx);
        float inv = 1.f/(p0+p1);
        float a0 = p0*inv, a1 = p1*inv;
        int c = 2*h2+d;
        float wfv = wf[c*2+ee];
        A[d]  = fmaf(wfv, a0*av[0], A[d]);
        Bc[d] = fmaf(wfv, a1*av[1], Bc[d]);
        Cc[d] = fmaf(wfv, fmaf(a0,bv[0],a1*bv[1]), Cc[d]);
      }
    }
    coef[0]=A[0]; coef[1]=Bc[0]; coef[2]=Cc[0]+bf[2*h2];
    coef[3]=A[1]; coef[4]=Bc[1]; coef[5]=Cc[1]+bf[2*h2+1];
  }
  __syncthreads();
  float A0=coef[0],B0=coef[1],C0=coef[2],A1=coef[3],B1=coef[4],C1=coef[5];
  float* o0 = g_y5 + (b*64 + h2)*1024;
  float* o1 = g_y5 + (b*64 + 32 + h2)*1024;
  for (int i=t;i<1024;i+=256){
    float a = ch0[i], c = ch1[i];
    o0[i] = fmaf(A0,a,fmaf(B0,c,C0));
    o1[i] = fmaf(A1,a,fmaf(B1,c,C1));
  }
}

// ---------------- K3: spatial attention via Fourier-Bessel moments ----------------
// score = exp(t*cos(theta_q - phi_k));  e^{t cos a} = I0(t) + 2*sum_j I_j(t) cos(j a)
// => den/num are linear in 44 circular moments of the keys (J=8 terms).
#define NJ 8
__global__ void k_spattn(const float* __restrict__ wqkv, const float* __restrict__ bqkv,
                         const float* __restrict__ tvec){
  int h = blockIdx.x, b = blockIdx.y;
  int ee = h>>5;
  int c0 = (h&31)*2;
  __shared__ float2 qs[1024];
  __shared__ float red[8][44];
  __shared__ float mom[44];
  __shared__ float wj[NJ];
  int t = threadIdx.x;
  if (t==0){
    float tt = tvec[h];
    double hx = 0.5*(double)tt;
    double x2 = hx*hx;
    #pragma unroll
    for (int j=0;j<NJ;j++){
      double p = 1.0;
      for (int i=0;i<j;i++) p *= hx/(double)(i+1);
      double s = 0.0;
      for (int k=0;k<14;k++){ s += p; p *= x2/((double)(k+1)*(double)(k+1+j)); }
      wj[j] = (float)((j==0?1.0:2.0)*s);
    }
  }
  float aq0=wqkv[c0*6+ee],     bq0=bqkv[c0*6+ee];
  float aq1=wqkv[(c0+1)*6+ee], bq1=bqkv[(c0+1)*6+ee];
  float ak0=wqkv[c0*6+2+ee],     bk0=bqkv[c0*6+2+ee];
  float ak1=wqkv[(c0+1)*6+2+ee], bk1=bqkv[(c0+1)*6+2+ee];
  float av0=wqkv[c0*6+4+ee],     bv0=bqkv[c0*6+4+ee];
  float av1=wqkv[(c0+1)*6+4+ee], bv1=bqkv[(c0+1)*6+4+ee];
  const float* x0p = g_y5 + (b*64 + c0)*1024;
  const float* x1p = x0p + 1024;
  // acc layout: [0]=Sum v0, [1]=Sum v1; for j=1..7 base=2+6*(j-1):
  //   +0: Sum cos(j*phi), +1: c*v0, +2: c*v1, +3: Sum sin(j*phi), +4: s*v0, +5: s*v1
  float acc[44];
  #pragma unroll
  for (int v=0;v<44;v++) acc[v]=0.f;
  #pragma unroll
  for (int q=0;q<4;q++){
    int i = t + q*256;
    float x0=x0p[i], x1=x1p[i];
    float qx = fmaf(aq0,x0,bq0), qy = fmaf(aq1,x1,bq1);
    float qi = 1.f/fmaxf(sqrtf(qx*qx+qy*qy),1e-12f);
    qs[i] = make_float2(qx*qi, qy*qi);
    float kx = fmaf(ak0,x0,bk0), ky = fmaf(ak1,x1,bk1);
    float ki = 1.f/fmaxf(sqrtf(kx*kx+ky*ky),1e-12f);
    float c1 = kx*ki, s1 = ky*ki;
    float v0 = fmaf(av0,x0,bv0), v1 = fmaf(av1,x1,bv1);
    acc[0]+=v0; acc[1]+=v1;
    float cj=c1, sj=s1;
    #pragma unroll
    for (int j=1;j<NJ;j++){
      int bse = 2+6*(j-1);
      acc[bse]   += cj;
      acc[bse+1]  = fmaf(cj,v0,acc[bse+1]);
      acc[bse+2]  = fmaf(cj,v1,acc[bse+2]);
      acc[bse+3] += sj;
      acc[bse+4]  = fmaf(sj,v0,acc[bse+4]);
      acc[bse+5]  = fmaf(sj,v1,acc[bse+5]);
      float cn = fmaf(cj,c1,-sj*s1);
      float sn = fmaf(sj,c1, cj*s1);
      cj=cn; sj=sn;
    }
  }
  // block reduce 44 values
  #pragma unroll
  for (int v=0;v<44;v++){
    float s = acc[v];
    #pragma unroll
    for (int off=16;off;off>>=1) s += __shfl_down_sync(0xffffffffu,s,off);
    if ((t&31)==0) red[t>>5][v] = s;
  }
  __syncthreads();
  if (t<44){
    float s=0.f;
    #pragma unroll
    for (int w=0;w<8;w++) s += red[w][t];
    mom[t]=s;
  }
  __syncthreads();
  float M[44];
  #pragma unroll
  for (int v=0;v<44;v++) M[v]=mom[v];
  float W[NJ];
  #pragma unroll
  for (int j=0;j<NJ;j++) W[j]=wj[j];
  float* ob = g_os + (b*64+h)*2048;
  #pragma unroll
  for (int q=0;q<4;q++){
    int n = t + q*256;
    float2 qq = qs[n];
    float c1=qq.x, s1=qq.y;
    float den = W[0]*1024.f;
    float o0  = W[0]*M[0];
    float o1  = W[0]*M[1];
    float cj=c1, sj=s1;
    #pragma unroll
    for (int j=1;j<NJ;j++){
      int bse = 2+6*(j-1);
      float w = W[j];
      den = fmaf(w, fmaf(cj,M[bse],   sj*M[bse+3]), den);
      o0  = fmaf(w, fmaf(cj,M[bse+1], sj*M[bse+4]), o0);
      o1  = fmaf(w, fmaf(cj,M[bse+2], sj*M[bse+5]), o1);
      float cn = fmaf(cj,c1,-sj*s1);
      float sn = fmaf(sj,c1, cj*s1);
      cj=cn; sj=sn;
    }
    float inv = 1.f/den;
    ob[n]      = o0*inv;
    ob[1024+n] = o1*inv;
  }
}

// ---------------- K4: group fuse + un1 (grouped 1x1) + pixel shuffle + un2 ----------------
__global__ void k_fuse(const float* __restrict__ wf, const float* __restrict__ bf,
                       const float* __restrict__ w1, const float* __restrict__ b1,
                       const float* __restrict__ w2, const float* __restrict__ b2,
                       float* __restrict__ out){
  __shared__ float y6s[64][65];
  __shared__ float4 wu2[512];
  int t = threadIdx.x;
  int b = blockIdx.y;
  int n0 = blockIdx.x*64;
  for (int i=t;i<512;i+=256) wu2[i] = ((const float4*)w2)[i];
  for (int j=t;j<4096;j+=256){
    int pos = j&63, c = j>>6;
    int n = n0+pos;
    float o0 = g_os[((b*64 + (c>>1))*2 + (c&1))*1024 + n];
    float o1 = g_os[((b*64 + 32 + (c>>1))*2 + (c&1))*1024 + n];
    y6s[pos][c] = fmaf(wf[c*2],o0, fmaf(wf[c*2+1],o1, bf[c]));
  }
  __syncthreads();
  int pos = t>>2, r = t&3;
  float z[32];
  #pragma unroll
  for (int cc=0;cc<32;cc++){
    int o2 = 4*cc+r;
    z[cc] = fmaf(w1[o2*2], y6s[pos][2*cc], fmaf(w1[o2*2+1], y6s[pos][2*cc+1], b1[o2]));
  }
  int n = n0+pos;
  int hh = n>>5, ww = n&31;
  float* outp = out + (b<<18) + ((2*hh + (r>>1))<<6) + 2*ww + (r&1);
  #pragma unroll 2
  for (int o=0;o<64;o++){
    float acc = b2[o];
    #pragma unroll
    for (int q8=0;q8<8;q8++){
      float4 wv = wu2[o*8+q8];
      acc = fmaf(wv.x,z[q8*4+0], fmaf(wv.y,z[q8*4+1], fmaf(wv.z,z[q8*4+2], fmaf(wv.w,z[q8*4+3], acc))));
    }
    outp[o<<12] = acc;
  }
}

extern "C" void kernel_launch(void* const* d_in, const int* in_sizes, int n_in,
                              void* d_out, int out_size){
  const float* x       = (const float*)d_in[0];
  const float* w_sq1   = (const float*)d_in[1];
  const float* b_sq1   = (const float*)d_in[2];
  const float* w_sq2   = (const float*)d_in[3];
  const float* b_sq2   = (const float*)d_in[4];
  const float* ca_wqkv = (const float*)d_in[5];
  const float* ca_bqkv = (const float*)d_in[6];
  const float* ca_t    = (const float*)d_in[7];
  const float* ca_wf   = (const float*)d_in[8];
  const float* ca_bf   = (const float*)d_in[9];
  const float* sa_wqkv = (const float*)d_in[10];
  const float* sa_bqkv = (const float*)d_in[11];
  const float* sa_t    = (const float*)d_in[12];
  const float* sa_wf   = (const float*)d_in[13];
  const float* sa_bf   = (const float*)d_in[14];
  const float* w_un1   = (const float*)d_in[15];
  const float* b_un1   = (const float*)d_in[16];
  const float* w_un2   = (const float*)d_in[17];
  const float* b_un2   = (const float*)d_in[18];
  float* out = (float*)d_out;

  k_squeeze1<<<dim3(16,4,2),256>>>(x, w_sq1, b_sq1);
  k_chattn<<<dim3(32,2),256>>>(w_sq2, b_sq2, ca_wqkv, ca_bqkv, ca_t, ca_wf, ca_bf);
  k_spattn<<<dim3(64,2),256>>>(sa_wqkv, sa_bqkv, sa_t);
  k_fuse<<<dim3(16,2),256>>>(sa_wf, sa_bf, w_un1, b_un1, w_un2, b_un2, out);
}

// round 3
// speedup vs baseline: 2.8097x; 2.6347x over previous
#include <cuda_runtime.h>

// ---------------- scratch (no allocations allowed) ----------------
__device__ float g_y1a[2*32*4096];     // after pointwise squeeze (b,32,64,64)
__device__ float g_y5[2*64*1024];      // after channel attn + nidx perm
__device__ float g_os[2*64*2*1024];    // spatial attn output per head (b,h,d,n)

// ---------------- K1: pointwise squeeze 64->32 over (2,64,64,64) ----------------
__global__ void k_squeeze1(const float* __restrict__ x, const float* __restrict__ w,
                           const float* __restrict__ bias){
  __shared__ float ws[512];
  int t = threadIdx.x;
  int og = blockIdx.y, b = blockIdx.z;
  for (int i=t;i<512;i+=256) ws[i] = w[og*512 + i];
  __syncthreads();
  int pos = blockIdx.x*256 + t;
  float acc[8];
  #pragma unroll
  for (int oo=0;oo<8;oo++) acc[oo] = bias[og*8+oo];
  const float* xp = x + b*262144 + pos;
  #pragma unroll 4
  for (int c=0;c<64;c++){
    float xv = xp[c<<12];
    #pragma unroll
    for (int oo=0;oo<8;oo++) acc[oo] = fmaf(xv, ws[oo*64+c], acc[oo]);
  }
  #pragma unroll
  for (int oo=0;oo<8;oo++) g_y1a[((b*32+og*8+oo)<<12)+pos] = acc[oo];
}

// ---------------- K2: depthwise 2x2 s2 (fused) + channel attention via moments ----------------
__global__ void k_chattn(const float* __restrict__ w2, const float* __restrict__ b2,
                         const float* __restrict__ wqkv, const float* __restrict__ bqkv,
                         const float* __restrict__ tvec, const float* __restrict__ wf,
                         const float* __restrict__ bf){
  int h2 = blockIdx.x, b = blockIdx.y;       // h2 in [0,32)
  __shared__ float ch0[1024], ch1[1024];
  __shared__ float red[8][5];
  __shared__ float coef[6];
  int t = threadIdx.x;
  int oc0 = h2, oc1 = h2 + 32;
  int g0 = oc0>>1, g1 = oc1>>1;
  const float* s0b = g_y1a + ((b*32+g0)<<12);
  const float* s1b = g_y1a + ((b*32+g1)<<12);
  float w00=w2[oc0*4],w01=w2[oc0*4+1],w02=w2[oc0*4+2],w03=w2[oc0*4+3],bb0=b2[oc0];
  float w10=w2[oc1*4],w11=w2[oc1*4+1],w12=w2[oc1*4+2],w13=w2[oc1*4+3],bb1=b2[oc1];
  float s0=0.f,s1=0.f,m00=0.f,m01=0.f,m11=0.f;
  for (int i=t;i<1024;i+=256){
    int hh=i>>5, ww=i&31;
    int off = (hh<<7) + (ww<<1);
    const float* p0 = s0b + off;
    const float* p1 = s1b + off;
    float a = bb0 + p0[0]*w00 + p0[1]*w01 + p0[64]*w02 + p0[65]*w03;
    float c = bb1 + p1[0]*w10 + p1[1]*w11 + p1[64]*w12 + p1[65]*w13;
    ch0[i]=a; ch1[i]=c;
    s0+=a; s1+=c; m00=fmaf(a,a,m00); m01=fmaf(a,c,m01); m11=fmaf(c,c,m11);
  }
  #pragma unroll
  for (int off=16;off;off>>=1){
    s0 += __shfl_down_sync(0xffffffffu,s0,off);
    s1 += __shfl_down_sync(0xffffffffu,s1,off);
    m00+= __shfl_down_sync(0xffffffffu,m00,off);
    m01+= __shfl_down_sync(0xffffffffu,m01,off);
    m11+= __shfl_down_sync(0xffffffffu,m11,off);
  }
  if ((t&31)==0){ int w=t>>5; red[w][0]=s0; red[w][1]=s1; red[w][2]=m00; red[w][3]=m01; red[w][4]=m11; }
  __syncthreads();
  if (t==0){
    float S1v[2]={0.f,0.f}, S200=0.f,S201=0.f,S211=0.f;
    for (int w=0;w<8;w++){ S1v[0]+=red[w][0]; S1v[1]+=red[w][1]; S200+=red[w][2]; S201+=red[w][3]; S211+=red[w][4]; }
    float S2[2][2]; S2[0][0]=S200; S2[0][1]=S201; S2[1][0]=S201; S2[1][1]=S211;
    float A[2]={0.f,0.f}, Bc[2]={0.f,0.f}, Cc[2]={0.f,0.f};
    #pragma unroll
    for (int ee=0;ee<2;ee++){
      int h = h2 + 32*ee;
      float th = tvec[h];
      float aq[2],bq[2],ak[2],bk[2],av[2],bv[2],nq[2],nk[2];
      #pragma unroll
      for (int d=0;d<2;d++){
        int cd = 2*h2+d;
        aq[d]=wqkv[cd*6+ee];   bq[d]=bqkv[cd*6+ee];
        ak[d]=wqkv[cd*6+2+ee]; bk[d]=bqkv[cd*6+2+ee];
        av[d]=wqkv[cd*6+4+ee]; bv[d]=bqkv[cd*6+4+ee];
        nq[d]=fmaxf(sqrtf(fmaxf(aq[d]*aq[d]*S2[d][d]+2.f*aq[d]*bq[d]*S1v[d]+bq[d]*bq[d]*1024.f,0.f)),1e-12f);
        nk[d]=fmaxf(sqrtf(fmaxf(ak[d]*ak[d]*S2[d][d]+2.f*ak[d]*bk[d]*S1v[d]+bk[d]*bk[d]*1024.f,0.f)),1e-12f);
      }
      #pragma unroll
      for (int d=0;d<2;d++){
        float l[2];
        #pragma unroll
        for (int e=0;e<2;e++){
          float dot = aq[d]*ak[e]*S2[d][e] + aq[d]*bk[e]*S1v[d] + bq[d]*ak[e]*S1v[e] + bq[d]*bk[e]*1024.f;
          l[e] = dot/(nq[d]*nk[e])*th;
        }
        float mx = fmaxf(l[0],l[1]);
        float p0 = __expf(l[0]-mx), p1 = __expf(l[1]-mx);
        float inv = 1.f/(p0+p1);
        float a0 = p0*inv, a1 = p1*inv;
        int c = 2*h2+d;
        float wfv = wf[c*2+ee];
        A[d]  = fmaf(wfv, a0*av[0], A[d]);
        Bc[d] = fmaf(wfv, a1*av[1], Bc[d]);
        Cc[d] = fmaf(wfv, fmaf(a0,bv[0],a1*bv[1]), Cc[d]);
      }
    }
    coef[0]=A[0]; coef[1]=Bc[0]; coef[2]=Cc[0]+bf[2*h2];
    coef[3]=A[1]; coef[4]=Bc[1]; coef[5]=Cc[1]+bf[2*h2+1];
  }
  __syncthreads();
  float A0=coef[0],B0=coef[1],C0=coef[2],A1=coef[3],B1=coef[4],C1=coef[5];
  float* o0 = g_y5 + (b*64 + h2)*1024;
  float* o1 = g_y5 + (b*64 + 32 + h2)*1024;
  for (int i=t;i<1024;i+=256){
    float a = ch0[i], c = ch1[i];
    o0[i] = fmaf(A0,a,fmaf(B0,c,C0));
    o1[i] = fmaf(A1,a,fmaf(B1,c,C1));
  }
}

// ---------------- K3: spatial attention via Fourier-Bessel moments ----------------
// score = exp(t*cos(theta_q - phi_k));  e^{t cos a} = I0(t) + 2*sum_j I_j(t) cos(j a)
#define NJ 8
__global__ void k_spattn(const float* __restrict__ wqkv, const float* __restrict__ bqkv,
                         const float* __restrict__ tvec){
  int h = blockIdx.x, b = blockIdx.y;
  int ee = h>>5;
  int c0 = (h&31)*2;
  __shared__ float2 qs[1024];
  __shared__ float red[8][44];
  __shared__ float mom[44];
  __shared__ float wj[NJ];
  int t = threadIdx.x;
  // fp32 Bessel I_j(t) series, one j per thread (parallel, no DP divisions)
  if (t < NJ){
    float tt = tvec[h];
    float hx = 0.5f*tt;
    float x2 = hx*hx;
    int j = t;
    float p = 1.f;
    for (int i=0;i<j;i++) p *= hx/(float)(i+1);
    float s = 0.f;
    #pragma unroll
    for (int k=0;k<14;k++){ s += p; p *= x2/((float)(k+1)*(float)(k+1+j)); }
    wj[j] = (j==0?1.f:2.f)*s;
  }
  float aq0=wqkv[c0*6+ee],     bq0=bqkv[c0*6+ee];
  float aq1=wqkv[(c0+1)*6+ee], bq1=bqkv[(c0+1)*6+ee];
  float ak0=wqkv[c0*6+2+ee],     bk0=bqkv[c0*6+2+ee];
  float ak1=wqkv[(c0+1)*6+2+ee], bk1=bqkv[(c0+1)*6+2+ee];
  float av0=wqkv[c0*6+4+ee],     bv0=bqkv[c0*6+4+ee];
  float av1=wqkv[(c0+1)*6+4+ee], bv1=bqkv[(c0+1)*6+4+ee];
  const float* x0p = g_y5 + (b*64 + c0)*1024;
  const float* x1p = x0p + 1024;
  // acc layout: [0]=Sum v0, [1]=Sum v1; for j>=1 base=2+6*(j-1):
  //   +0: Sum cos(j phi), +1: c*v0, +2: c*v1, +3: Sum sin(j phi), +4: s*v0, +5: s*v1
  float acc[44];
  #pragma unroll
  for (int v=0;v<44;v++) acc[v]=0.f;
  #pragma unroll
  for (int q=0;q<4;q++){
    int i = t + q*256;
    float x0=x0p[i], x1=x1p[i];
    float qx = fmaf(aq0,x0,bq0), qy = fmaf(aq1,x1,bq1);
    float qi = 1.f/fmaxf(sqrtf(qx*qx+qy*qy),1e-12f);
    qs[i] = make_float2(qx*qi, qy*qi);
    float kx = fmaf(ak0,x0,bk0), ky = fmaf(ak1,x1,bk1);
    float ki = 1.f/fmaxf(sqrtf(kx*kx+ky*ky),1e-12f);
    float c1 = kx*ki, s1 = ky*ki;
    float v0 = fmaf(av0,x0,bv0), v1 = fmaf(av1,x1,bv1);
    acc[0]+=v0; acc[1]+=v1;
    float cj=c1, sj=s1;
    #pragma unroll
    for (int j=1;j<NJ;j++){
      int bse = 2+6*(j-1);
      acc[bse]   += cj;
      acc[bse+1]  = fmaf(cj,v0,acc[bse+1]);
      acc[bse+2]  = fmaf(cj,v1,acc[bse+2]);
      acc[bse+3] += sj;
      acc[bse+4]  = fmaf(sj,v0,acc[bse+4]);
      acc[bse+5]  = fmaf(sj,v1,acc[bse+5]);
      float cn = fmaf(cj,c1,-sj*s1);
      float sn = fmaf(sj,c1, cj*s1);
      cj=cn; sj=sn;
    }
  }
  #pragma unroll
  for (int v=0;v<44;v++){
    float s = acc[v];
    #pragma unroll
    for (int off=16;off;off>>=1) s += __shfl_down_sync(0xffffffffu,s,off);
    if ((t&31)==0) red[t>>5][v] = s;
  }
  __syncthreads();
  if (t<44){
    float s=0.f;
    #pragma unroll
    for (int w=0;w<8;w++) s += red[w][t];
    mom[t]=s;
  }
  __syncthreads();
  float M[44];
  #pragma unroll
  for (int v=0;v<44;v++) M[v]=mom[v];
  float W[NJ];
  #pragma unroll
  for (int j=0;j<NJ;j++) W[j]=wj[j];
  float* ob = g_os + (b*64+h)*2048;
  #pragma unroll
  for (int q=0;q<4;q++){
    int n = t + q*256;
    float2 qq = qs[n];
    float c1=qq.x, s1=qq.y;
    float den = W[0]*1024.f;
    float o0  = W[0]*M[0];
    float o1  = W[0]*M[1];
    float cj=c1, sj=s1;
    #pragma unroll
    for (int j=1;j<NJ;j++){
      int bse = 2+6*(j-1);
      float w = W[j];
      den = fmaf(w, fmaf(cj,M[bse],   sj*M[bse+3]), den);
      o0  = fmaf(w, fmaf(cj,M[bse+1], sj*M[bse+4]), o0);
      o1  = fmaf(w, fmaf(cj,M[bse+2], sj*M[bse+5]), o1);
      float cn = fmaf(cj,c1,-sj*s1);
      float sn = fmaf(sj,c1, cj*s1);
      cj=cn; sj=sn;
    }
    float inv = 1.f/den;
    ob[n]      = o0*inv;
    ob[1024+n] = o1*inv;
  }
}

// ---------------- K4: group fuse + un1 + pixel shuffle + un2 (parallel/ILP rework) ----------------
__global__ void k_fuse(const float* __restrict__ wf, const float* __restrict__ bf,
                       const float* __restrict__ w1, const float* __restrict__ b1,
                       const float* __restrict__ w2, const float* __restrict__ b2,
                       float* __restrict__ out){
  __shared__ float  y6s[16][64];     // [pos][c]
  __shared__ float  zs[64][33];      // [idx = r*16+pos][cc], padded
  __shared__ float4 w2t4[32][17];    // [q][o/4], padded; transposed un2 weights
  int t = threadIdx.x;
  int b = blockIdx.y;
  int n0 = blockIdx.x*16;
  // load w2 (64x32, o-major) transposed into shared
  {
    float* w2f = (float*)w2t4;       // index: q*68 + o
    for (int i=t;i<2048;i+=256){
      int o = i>>5, q = i&31;
      w2f[q*68 + o] = w2[i];
    }
  }
  // phase A: group fuse -> y6s
  for (int j=t;j<1024;j+=256){
    int pos = j&15, c = j>>4;
    int n = n0+pos;
    float o0 = g_os[((b*64 + (c>>1))*2 + (c&1))*1024 + n];
    float o1 = g_os[((b*64 + 32 + (c>>1))*2 + (c&1))*1024 + n];
    y6s[pos][c] = fmaf(wf[c*2],o0, fmaf(wf[c*2+1],o1, bf[c]));
  }
  __syncthreads();
  // phase B: un1 grouped 1x1 -> zs
  for (int j=t;j<2048;j+=256){
    int cc = j&31, idx = j>>5;        // idx = r*16+pos
    int r = idx>>4, pos = idx&15;
    int o2 = 4*cc + r;
    zs[idx][cc] = fmaf(w1[o2*2], y6s[pos][2*cc], fmaf(w1[o2*2+1], y6s[pos][2*cc+1], b1[o2]));
  }
  __syncthreads();
  // phase C: un2, 16 independent accumulators per thread
  int og = t>>6, idx = t&63;
  int r = idx>>4, pos = idx&15;
  float acc[16];
  #pragma unroll
  for (int oo=0;oo<16;oo++) acc[oo] = b2[og*16+oo];
  #pragma unroll 4
  for (int q=0;q<32;q++){
    float zq = zs[idx][q];
    #pragma unroll
    for (int k4=0;k4<4;k4++){
      float4 wv = w2t4[q][og*4 + k4];
      acc[k4*4+0] = fmaf(zq, wv.x, acc[k4*4+0]);
      acc[k4*4+1] = fmaf(zq, wv.y, acc[k4*4+1]);
      acc[k4*4+2] = fmaf(zq, wv.z, acc[k4*4+2]);
      acc[k4*4+3] = fmaf(zq, wv.w, acc[k4*4+3]);
    }
  }
  int n = n0+pos;
  int hh = n>>5, ww = n&31;
  float* outp = out + (b<<18) + ((2*hh + (r>>1))<<6) + 2*ww + (r&1);
  #pragma unroll
  for (int oo=0;oo<16;oo++)
    outp[(og*16+oo)<<12] = acc[oo];
}

extern "C" void kernel_launch(void* const* d_in, const int* in_sizes, int n_in,
                              void* d_out, int out_size){
  const float* x       = (const float*)d_in[0];
  const float* w_sq1   = (const float*)d_in[1];
  const float* b_sq1   = (const float*)d_in[2];
  const float* w_sq2   = (const float*)d_in[3];
  const float* b_sq2   = (const float*)d_in[4];
  const float* ca_wqkv = (const float*)d_in[5];
  const float* ca_bqkv = (const float*)d_in[6];
  const float* ca_t    = (const float*)d_in[7];
  const float* ca_wf   = (const float*)d_in[8];
  const float* ca_bf   = (const float*)d_in[9];
  const float* sa_wqkv = (const float*)d_in[10];
  const float* sa_bqkv = (const float*)d_in[11];
  const float* sa_t    = (const float*)d_in[12];
  const float* sa_wf   = (const float*)d_in[13];
  const float* sa_bf   = (const float*)d_in[14];
  const float* w_un1   = (const float*)d_in[15];
  const float* b_un1   = (const float*)d_in[16];
  const float* w_un2   = (const float*)d_in[17];
  const float* b_un2   = (const float*)d_in[18];
  float* out = (float*)d_out;

  k_squeeze1<<<dim3(16,4,2),256>>>(x, w_sq1, b_sq1);
  k_chattn<<<dim3(32,2),256>>>(w_sq2, b_sq2, ca_wqkv, ca_bqkv, ca_t, ca_wf, ca_bf);
  k_spattn<<<dim3(64,2),256>>>(sa_wqkv, sa_bqkv, sa_t);
  k_fuse<<<dim3(64,2),256>>>(sa_wf, sa_bf, w_un1, b_un1, w_un2, b_un2, out);
}